// round 14
// baseline (speedup 1.0000x reference)
#include <cuda_runtime.h>
#include <cuda_fp16.h>
#include <cstdint>

#define BATCH  2
#define SEQ    2048
#define DMODEL 2048
#define NHEADS 16
#define DKK    128
#define MTOT   (BATCH * SEQ)

#define N_X  ((size_t)MTOT * DMODEL)     // 8388608
#define N_WQ ((size_t)DMODEL * DMODEL)   // 4194304
#define N_WK ((size_t)DMODEL * DKK)      // 262144

// Scratch (allocation-free rule: device globals)
__device__ __half g_xh [N_X];
__device__ __half g_wqh[N_WQ];
__device__ __half g_wkh[N_WK];
__device__ __half g_wvh[N_WK];
__device__ __half g_woh[N_WQ];
__device__ __half g_kh [(size_t)MTOT * DKK];
__device__ __half g_vh [(size_t)MTOT * DKK];
__device__ __half g_ah [N_X];            // attention out fp16
__device__ unsigned g_kvdone;            // kv-CTA completion counter

#define KV_CTAS 256

// ---------------------------------------------------------------------------
// helpers
// ---------------------------------------------------------------------------
__device__ __forceinline__ uint32_t smem_u32(const void* p) {
    uint32_t a;
    asm("{ .reg .u64 t; cvta.to.shared.u64 t, %1; cvt.u32.u64 %0, t; }" : "=r"(a) : "l"(p));
    return a;
}
#define CP16(dst, src) \
    asm volatile("cp.async.cg.shared.global [%0], [%1], 16;" :: "r"(dst), "l"(src) : "memory")
#define CPCOMMIT() asm volatile("cp.async.commit_group;" ::: "memory")
#define CPWAIT(n)  asm volatile("cp.async.wait_group %0;" :: "n"(n) : "memory")

__device__ __forceinline__ void ldsm4(uint32_t* r, uint32_t a) {
    asm volatile("ldmatrix.sync.aligned.m8n8.x4.shared.b16 {%0,%1,%2,%3}, [%4];"
                 : "=r"(r[0]), "=r"(r[1]), "=r"(r[2]), "=r"(r[3]) : "r"(a));
}
__device__ __forceinline__ void ldsm4t(uint32_t* r, uint32_t a) {
    asm volatile("ldmatrix.sync.aligned.m8n8.x4.trans.shared.b16 {%0,%1,%2,%3}, [%4];"
                 : "=r"(r[0]), "=r"(r[1]), "=r"(r[2]), "=r"(r[3]) : "r"(a));
}
__device__ __forceinline__ void mma16816(float* d, const uint32_t* a, const uint32_t* b) {
    asm volatile(
        "mma.sync.aligned.m16n8k16.row.col.f32.f16.f16.f32 "
        "{%0,%1,%2,%3},{%4,%5,%6,%7},{%8,%9},{%0,%1,%2,%3};"
        : "+f"(d[0]), "+f"(d[1]), "+f"(d[2]), "+f"(d[3])
        : "r"(a[0]), "r"(a[1]), "r"(a[2]), "r"(a[3]), "r"(b[0]), "r"(b[1]));
}
__device__ __forceinline__ void mma16816b(float* d, const uint32_t* a,
                                          uint32_t b0, uint32_t b1) {
    asm volatile(
        "mma.sync.aligned.m16n8k16.row.col.f32.f16.f16.f32 "
        "{%0,%1,%2,%3},{%4,%5,%6,%7},{%8,%9},{%0,%1,%2,%3};"
        : "+f"(d[0]), "+f"(d[1]), "+f"(d[2]), "+f"(d[3])
        : "r"(a[0]), "r"(a[1]), "r"(a[2]), "r"(a[3]), "r"(b0), "r"(b1));
}
__device__ __forceinline__ uint32_t packh2(float lo, float hi) {
    __half2 h = __floats2half2_rn(lo, hi);
    return *(uint32_t*)&h;
}

// ---------------------------------------------------------------------------
// fused fp32 -> fp16: all five tensors in one launch (+ resets kv flag)
// ---------------------------------------------------------------------------
#define F2H_TOTAL (N_X + N_WQ + N_WK + N_WK + N_WQ)   // 17301504

__global__ __launch_bounds__(256) void f2h_all(
    const float* __restrict__ x,  const float* __restrict__ wq,
    const float* __restrict__ wk, const float* __restrict__ wv,
    const float* __restrict__ wo)
{
    if (blockIdx.x == 0 && threadIdx.x == 0) g_kvdone = 0;
    size_t i = ((size_t)blockIdx.x * 256 + threadIdx.x) * 4;
    const float* s;
    __half* d;
    size_t off;
    if (i < N_X)                            { s = x;  d = g_xh;  off = i; }
    else if (i < N_X + N_WQ)                { s = wq; d = g_wqh; off = i - N_X; }
    else if (i < N_X + N_WQ + N_WK)         { s = wk; d = g_wkh; off = i - N_X - N_WQ; }
    else if (i < N_X + N_WQ + 2 * N_WK)     { s = wv; d = g_wvh; off = i - N_X - N_WQ - N_WK; }
    else                                    { s = wo; d = g_woh; off = i - N_X - N_WQ - 2 * N_WK; }
    float4 v = *(const float4*)(s + off);
    __half2* dp = (__half2*)(d + off);
    dp[0] = __floats2half2_rn(v.x, v.y);
    dp[1] = __floats2half2_rn(v.z, v.w);
}

// ---------------------------------------------------------------------------
// GEMM tile geometry
// ---------------------------------------------------------------------------
#define GS_A 5120             // 64 rows * 80B
#define GS_B 8704             // 32 rows * 272B
#define GS_STAGE (GS_A + GS_B)    // 13824
#define GEMM_SMEM (4 * GS_STAGE)  // 55296

// BM=32 variant (kv path)
#define G32_A 2560            // 32 rows * 80B
#define G32_STAGE (G32_A + GS_B)  // 11264

#define GEMM_MAINLOOP()                                                        \
    stage(0, 0); CPCOMMIT();                                                   \
    stage(1, 1); CPCOMMIT();                                                   \
    stage(2, 2); CPCOMMIT();                                                   \
    CPWAIT(2); __syncthreads();                                                \
    ldfr(0, 0);                                                                \
    for (int c = 0; c < NC; c += 2) {                                          \
        CPWAIT(1); __syncthreads();                                            \
        ldfr(1, (c + 1) & 3);                                                  \
        if (c + 3 < NC) stage(c + 3, (c + 3) & 3);                             \
        CPCOMMIT();                                                            \
        domma(0);                                                              \
        if (c + 2 < NC) {                                                      \
            CPWAIT(1); __syncthreads();                                        \
            ldfr(0, (c + 2) & 3);                                              \
        }                                                                      \
        if (c + 4 < NC) stage(c + 4, (c + 4) & 3);                             \
        CPCOMMIT();                                                            \
        domma(1);                                                              \
    }

// ---------------------------------------------------------------------------
// Output projection GEMM: out(fp32) = ah @ woh + b_o  (BM=64, BN=128)
// ---------------------------------------------------------------------------
__global__ __launch_bounds__(128, 2) void gemm_o(
    const __half* __restrict__ A, const float* __restrict__ bias,
    float* __restrict__ C)
{
    extern __shared__ char smc[];
    const uint32_t sb = smem_u32(smc);

    const int tid  = threadIdx.x;
    const int lane = tid & 31;
    const int wid  = tid >> 5;
    const int wm   = wid & 1;
    const int wn   = wid >> 1;
    const int N = DMODEL, K = DMODEL, NC = K / 32;
    const int rowBase = blockIdx.y * 64;
    const int colBase = blockIdx.x * 128;

    auto stage = [&](int c, int s) {
        const int k0 = c * 32;
        const uint32_t sA = sb + s * GS_STAGE;
        const uint32_t sB = sA + GS_A;
#pragma unroll
        for (int i = 0; i < 2; i++) {
            int ch = tid + 128 * i;
            int r = ch >> 2, kc = ch & 3;
            CP16(sA + r * 80 + kc * 16, A + (size_t)(rowBase + r) * K + k0 + kc * 8);
        }
#pragma unroll
        for (int i = 0; i < 4; i++) {
            int ch = tid + 128 * i;
            int r = ch >> 4, nc = ch & 15;
            CP16(sB + r * 272 + nc * 16, g_woh + (size_t)(k0 + r) * N + colBase + nc * 8);
        }
    };

    float acc[2][8][4];
#pragma unroll
    for (int a = 0; a < 2; a++)
#pragma unroll
        for (int b = 0; b < 8; b++)
#pragma unroll
            for (int r = 0; r < 4; r++) acc[a][b][r] = 0.f;

    const uint32_t aOff = (wm * 32 + (lane & 15)) * 80 + (lane >> 4) * 16;
    const uint32_t bRow = (lane & 15) * 272;
    const uint32_t bCol = (wn * 64 + 8 * (lane >> 4)) * 2;

    uint32_t fa[2][2][2][4];
    uint32_t fb[2][2][4][4];

    auto ldfr = [&](int set, int bufi) {
        const uint32_t sA = sb + bufi * GS_STAGE;
        const uint32_t sB = sA + GS_A;
#pragma unroll
        for (int ks = 0; ks < 2; ks++) {
            ldsm4(fa[set][ks][0], sA + aOff + ks * 32);
            ldsm4(fa[set][ks][1], sA + aOff + 16 * 80 + ks * 32);
#pragma unroll
            for (int nbp = 0; nbp < 4; nbp++)
                ldsm4t(fb[set][ks][nbp], sB + bRow + ks * 16 * 272 + bCol + nbp * 32);
        }
    };
    auto domma = [&](int set) {
#pragma unroll
        for (int ks = 0; ks < 2; ks++)
#pragma unroll
            for (int nbp = 0; nbp < 4; nbp++) {
                mma16816(acc[0][2 * nbp],     fa[set][ks][0], fb[set][ks][nbp]);
                mma16816(acc[0][2 * nbp + 1], fa[set][ks][0], fb[set][ks][nbp] + 2);
                mma16816(acc[1][2 * nbp],     fa[set][ks][1], fb[set][ks][nbp]);
                mma16816(acc[1][2 * nbp + 1], fa[set][ks][1], fb[set][ks][nbp] + 2);
            }
    };

    GEMM_MAINLOOP();

    const int g = lane >> 2, q = lane & 3;
#pragma unroll
    for (int mb = 0; mb < 2; mb++) {
        int row = rowBase + wm * 32 + mb * 16 + g;
#pragma unroll
        for (int nb = 0; nb < 8; nb++) {
            int col = colBase + wn * 64 + nb * 8 + 2 * q;
            float b0 = bias[col], b1 = bias[col + 1];
            *(float2*)(C + (size_t)row * N + col) =
                make_float2(acc[mb][nb][0] + b0, acc[mb][nb][1] + b1);
            *(float2*)(C + (size_t)(row + 8) * N + col) =
                make_float2(acc[mb][nb][2] + b0, acc[mb][nb][3] + b1);
        }
    }
}

// ---------------------------------------------------------------------------
// COMBINED kv-projection + flash kernel, grid = 1280 CTAs:
//   bid 0..255   : K/V projection tile (BM=32), then release g_kvdone
//   bid 256..1279: flash (fused Q-proj -> acquire-wait kv -> attention)
// kv CTAs occupy wave-1 slots (first bids) and overlap flash Q-projection.
// ---------------------------------------------------------------------------
#define FITEM 17408                    // 64 rows * 272B
#define FQ_BYTES 17408
#define FLASH_SMEM (FQ_BYTES + 3 * FITEM)   // 69632 -> 3 CTAs/SM
#define NT (SEQ / 64)
#define QP_A 5120                      // x-chunk bytes within a ring buffer

__global__ __launch_bounds__(128, 3) void kv_flash(
    const float* __restrict__ b_q, const float* __restrict__ b_k,
    const float* __restrict__ b_v,
    float* __restrict__ Kc, float* __restrict__ Vc, float qscale)
{
    extern __shared__ char smc[];
    const uint32_t sb = smem_u32(smc);
    const int tid  = threadIdx.x;
    const int lane = tid & 31;
    const int wid  = tid >> 5;
    const int bid  = blockIdx.x;

    if (bid < KV_CTAS) {
        // ================= K/V projection (BM=32) =================
        const int wm = wid & 1, wn = wid >> 1;
        const int K = DMODEL, NC = K / 32;
        const bool isK = bid < 128;
        const int rowBase = (bid & 127) * 32;
        const __half* Bsel = isK ? g_wkh : g_wvh;
        const float* biasS = isK ? b_k : b_v;
        __half* Chf        = isK ? g_kh : g_vh;
        float* Cf          = isK ? Kc : Vc;
        const int N        = DKK;

        auto stage = [&](int c, int s) {
            const int k0 = c * 32;
            const uint32_t sA = sb + s * G32_STAGE;
            const uint32_t sB = sA + G32_A;
            {
                int r = tid >> 2, kc = tid & 3;
                CP16(sA + r * 80 + kc * 16,
                     g_xh + (size_t)(rowBase + r) * K + k0 + kc * 8);
            }
#pragma unroll
            for (int i = 0; i < 4; i++) {
                int ch = tid + 128 * i;
                int r = ch >> 4, nc = ch & 15;
                CP16(sB + r * 272 + nc * 16, Bsel + (size_t)(k0 + r) * N + nc * 8);
            }
        };

        float acc[8][4];
#pragma unroll
        for (int b = 0; b < 8; b++)
#pragma unroll
            for (int r = 0; r < 4; r++) acc[b][r] = 0.f;

        const uint32_t aOff = (wm * 16 + (lane & 15)) * 80 + (lane >> 4) * 16;
        const uint32_t bRow = (lane & 15) * 272;
        const uint32_t bCol = (wn * 64 + 8 * (lane >> 4)) * 2;

        uint32_t fa[2][2][4];
        uint32_t fb[2][2][4][4];

        auto ldfr = [&](int set, int bufi) {
            const uint32_t sA = sb + bufi * G32_STAGE;
            const uint32_t sB = sA + G32_A;
#pragma unroll
            for (int ks = 0; ks < 2; ks++) {
                ldsm4(fa[set][ks], sA + aOff + ks * 32);
#pragma unroll
                for (int nbp = 0; nbp < 4; nbp++)
                    ldsm4t(fb[set][ks][nbp], sB + bRow + ks * 16 * 272 + bCol + nbp * 32);
            }
        };
        auto domma = [&](int set) {
#pragma unroll
            for (int ks = 0; ks < 2; ks++)
#pragma unroll
                for (int nbp = 0; nbp < 4; nbp++) {
                    mma16816(acc[2 * nbp],     fa[set][ks], fb[set][ks][nbp]);
                    mma16816(acc[2 * nbp + 1], fa[set][ks], fb[set][ks][nbp] + 2);
                }
        };

        GEMM_MAINLOOP();

        const int g = lane >> 2, q = lane & 3;
        const int row = rowBase + wm * 16 + g;
#pragma unroll
        for (int nb = 0; nb < 8; nb++) {
            int col = wn * 64 + nb * 8 + 2 * q;
            float b0 = biasS[col], b1 = biasS[col + 1];
            float v0 = acc[nb][0] + b0, v1 = acc[nb][1] + b1;
            float v2 = acc[nb][2] + b0, v3 = acc[nb][3] + b1;
            *(__half2*)(Chf + (size_t)row * N + col)       = __floats2half2_rn(v0, v1);
            *(__half2*)(Chf + (size_t)(row + 8) * N + col) = __floats2half2_rn(v2, v3);
            *(float2*)(Cf + (size_t)row * N + col)       = make_float2(v0, v1);
            *(float2*)(Cf + (size_t)(row + 8) * N + col) = make_float2(v2, v3);
        }

        // release: make kh/vh visible, then signal
        __threadfence();
        __syncthreads();
        if (tid == 0) atomicAdd(&g_kvdone, 1u);
        return;
    }

    // ======================= flash path =======================
    const int f  = bid - KV_CTAS;
    const int q0 = (f & 31) * 64;
    const int h  = (f >> 5) & 15;
    const int b  = f >> 9;
    const size_t kvbase = (size_t)b * SEQ;
    const uint32_t sQ = sb;
    const uint32_t sR = sb + FQ_BYTES;

    // ---- fused Q projection (3-buffer ring, 1 barrier/chunk) ----
    {
        const int wm = wid & 1, wn = wid >> 1;
        const __half* Ax = g_xh + (size_t)(b * SEQ + q0) * DMODEL;

        auto stageQ = [&](int c, int s) {
            const int k0 = c * 32;
            const uint32_t sA = sR + s * FITEM;
            const uint32_t sB = sA + QP_A;
#pragma unroll
            for (int i = 0; i < 2; i++) {
                int ch = tid + 128 * i;
                int r = ch >> 2, kc = ch & 3;
                CP16(sA + r * 80 + kc * 16, Ax + (size_t)r * DMODEL + k0 + kc * 8);
            }
#pragma unroll
            for (int i = 0; i < 4; i++) {
                int ch = tid + 128 * i;
                int r = ch >> 4, nc = ch & 15;
                CP16(sB + r * 272 + nc * 16,
                     g_wqh + (size_t)(k0 + r) * DMODEL + h * DKK + nc * 8);
            }
        };

        float acc[2][8][4];
#pragma unroll
        for (int a = 0; a < 2; a++)
#pragma unroll
            for (int bb = 0; bb < 8; bb++)
#pragma unroll
                for (int r = 0; r < 4; r++) acc[a][bb][r] = 0.f;

        const uint32_t aOff = (wm * 32 + (lane & 15)) * 80 + (lane >> 4) * 16;
        const uint32_t bRow = (lane & 15) * 272;
        const uint32_t bCol = (wn * 64 + 8 * (lane >> 4)) * 2;

        stageQ(0, 0); CPCOMMIT();
        stageQ(1, 1); CPCOMMIT();

        for (int c = 0; c < DMODEL / 32; c++) {
            CPWAIT(1);
            __syncthreads();
            // stage into buf (c-1)%3, consumed last iteration -> safe
            if (c + 2 < DMODEL / 32) stageQ(c + 2, (c + 2) % 3);
            CPCOMMIT();
            const uint32_t sA = sR + (c % 3) * FITEM;
            const uint32_t sB = sA + QP_A;
#pragma unroll
            for (int ks = 0; ks < 2; ks++) {
                uint32_t a0[4], a1[4];
                ldsm4(a0, sA + aOff + ks * 32);
                ldsm4(a1, sA + aOff + 16 * 80 + ks * 32);
#pragma unroll
                for (int nbp = 0; nbp < 4; nbp++) {
                    uint32_t bf[4];
                    ldsm4t(bf, sB + bRow + ks * 16 * 272 + bCol + nbp * 32);
                    mma16816(acc[0][2 * nbp],     a0, bf);
                    mma16816(acc[0][2 * nbp + 1], a0, bf + 2);
                    mma16816(acc[1][2 * nbp],     a1, bf);
                    mma16816(acc[1][2 * nbp + 1], a1, bf + 2);
                }
            }
        }
        CPWAIT(0);
        __syncthreads();   // ring fully drained before epilogue/attention reuse

        // epilogue: bias + scale -> sQ (fp16, row-major 272B rows)
        const int g = lane >> 2, q = lane & 3;
#pragma unroll
        for (int mb = 0; mb < 2; mb++) {
            int row = wm * 32 + mb * 16 + g;
#pragma unroll
            for (int nb = 0; nb < 8; nb++) {
                int col = wn * 64 + nb * 8 + 2 * q;
                float bq0 = b_q[h * DKK + col], bq1 = b_q[h * DKK + col + 1];
                *(__half2*)(smc + row * 272 + col * 2) =
                    __floats2half2_rn((acc[mb][nb][0] + bq0) * qscale,
                                      (acc[mb][nb][1] + bq1) * qscale);
                *(__half2*)(smc + (row + 8) * 272 + col * 2) =
                    __floats2half2_rn((acc[mb][nb][2] + bq0) * qscale,
                                      (acc[mb][nb][3] + bq1) * qscale);
            }
        }
        __syncthreads();
    }

    // persistent Q fragments from sQ
    uint32_t qf[8][4];
    {
        const uint32_t qB = sQ + (wid * 16 + (lane & 15)) * 272 + (lane >> 4) * 16;
#pragma unroll
        for (int ks = 0; ks < 8; ks++) ldsm4(qf[ks], qB + ks * 32);
    }

    // ---- acquire-wait for K/V projection completion ----
    if (tid == 0) {
        unsigned v;
        do {
            asm volatile("ld.global.acquire.gpu.u32 %0, [%1];"
                         : "=r"(v) : "l"(&g_kvdone) : "memory");
        } while (v < (unsigned)KV_CTAS);
    }
    __syncthreads();

    // ---- K/V attention loop (3-buffer interleaved item ring) ----
    auto stageItem = [&](int j) {
        if (j < 2 * NT) {
            const uint32_t base = sR + (j % 3) * FITEM;
            const __half* src = (j & 1) ? g_vh : g_kh;
            const size_t rowg = kvbase + (size_t)(j >> 1) * 64;
#pragma unroll
            for (int i = 0; i < 8; i++) {
                int ch = tid + 128 * i;
                int r = ch >> 4, nc = ch & 15;
                CP16(base + r * 272 + nc * 16, src + (rowg + r) * DKK + nc * 8);
            }
        }
    };

    stageItem(0); CPCOMMIT();
    stageItem(1); CPCOMMIT();
    stageItem(2); CPCOMMIT();

    CPWAIT(2);       // K0 ready
    __syncthreads();

    float oA[16][4];
#pragma unroll
    for (int i = 0; i < 16; i++)
#pragma unroll
        for (int r = 0; r < 4; r++) oA[i][r] = 0.f;
    float m0 = -1e30f, m1 = -1e30f, l0 = 0.f, l1 = 0.f;

    const uint32_t kOff = (lane & 15) * 272 + (lane >> 4) * 16;
    const uint32_t vRow = (lane & 15) * 272;
    const uint32_t vCol = (lane >> 4) * 16;

    for (int t = 0; t < NT; t++) {
        const uint32_t kB = sR + ((2 * t) % 3) * FITEM;
        const uint32_t vB = sR + ((2 * t + 1) % 3) * FITEM;

        if (t > 0) { CPWAIT(2); __syncthreads(); }

        float sC[8][4];
#pragma unroll
        for (int i = 0; i < 8; i++)
#pragma unroll
            for (int r = 0; r < 4; r++) sC[i][r] = 0.f;
#pragma unroll
        for (int ks = 0; ks < 8; ks++) {
#pragma unroll
            for (int nbp = 0; nbp < 4; nbp++) {
                uint32_t bf[4];
                ldsm4(bf, kB + nbp * 16 * 272 + kOff + ks * 32);
                mma16816b(sC[2 * nbp],     qf[ks], bf[0], bf[2]);
                mma16816b(sC[2 * nbp + 1], qf[ks], bf[1], bf[3]);
            }
        }

        float mx0 = -1e30f, mx1 = -1e30f;
#pragma unroll
        for (int nb = 0; nb < 8; nb++) {
            mx0 = fmaxf(mx0, fmaxf(sC[nb][0], sC[nb][1]));
            mx1 = fmaxf(mx1, fmaxf(sC[nb][2], sC[nb][3]));
        }
        mx0 = fmaxf(mx0, __shfl_xor_sync(0xffffffffu, mx0, 1));
        mx0 = fmaxf(mx0, __shfl_xor_sync(0xffffffffu, mx0, 2));
        mx1 = fmaxf(mx1, __shfl_xor_sync(0xffffffffu, mx1, 1));
        mx1 = fmaxf(mx1, __shfl_xor_sync(0xffffffffu, mx1, 2));
        float mn0 = fmaxf(m0, mx0), mn1 = fmaxf(m1, mx1);
        float cr0 = exp2f(m0 - mn0), cr1 = exp2f(m1 - mn1);
        m0 = mn0; m1 = mn1;
        float rs0 = 0.f, rs1 = 0.f;
#pragma unroll
        for (int nb = 0; nb < 8; nb++) {
            sC[nb][0] = exp2f(sC[nb][0] - mn0);
            sC[nb][1] = exp2f(sC[nb][1] - mn0);
            sC[nb][2] = exp2f(sC[nb][2] - mn1);
            sC[nb][3] = exp2f(sC[nb][3] - mn1);
            rs0 += sC[nb][0] + sC[nb][1];
            rs1 += sC[nb][2] + sC[nb][3];
        }
        rs0 += __shfl_xor_sync(0xffffffffu, rs0, 1);
        rs0 += __shfl_xor_sync(0xffffffffu, rs0, 2);
        rs1 += __shfl_xor_sync(0xffffffffu, rs1, 1);
        rs1 += __shfl_xor_sync(0xffffffffu, rs1, 2);
        l0 = l0 * cr0 + rs0;
        l1 = l1 * cr1 + rs1;
#pragma unroll
        for (int db = 0; db < 16; db++) {
            oA[db][0] *= cr0; oA[db][1] *= cr0;
            oA[db][2] *= cr1; oA[db][3] *= cr1;
        }

        uint32_t pf[4][4];
#pragma unroll
        for (int s = 0; s < 4; s++) {
            pf[s][0] = packh2(sC[2 * s][0],     sC[2 * s][1]);
            pf[s][1] = packh2(sC[2 * s][2],     sC[2 * s][3]);
            pf[s][2] = packh2(sC[2 * s + 1][0], sC[2 * s + 1][1]);
            pf[s][3] = packh2(sC[2 * s + 1][2], sC[2 * s + 1][3]);
        }

        __syncthreads();
        stageItem(2 * t + 3);
        CPCOMMIT();
        CPWAIT(2);
        __syncthreads();

#pragma unroll
        for (int s = 0; s < 4; s++) {
#pragma unroll
            for (int dbp = 0; dbp < 8; dbp++) {
                uint32_t vf[4];
                ldsm4t(vf, vB + s * 16 * 272 + vRow + (dbp * 16) * 2 + vCol);
                mma16816(oA[2 * dbp],     pf[s], vf);
                mma16816(oA[2 * dbp + 1], pf[s], vf + 2);
            }
        }

        __syncthreads();
        stageItem(2 * t + 4);
        CPCOMMIT();
    }

    const float inv0 = 1.f / l0, inv1 = 1.f / l1;
    const int g = lane >> 2, q = lane & 3;
    const int row = q0 + wid * 16 + g;
    __half* Op = g_ah + (size_t)(b * SEQ + row) * DMODEL + h * DKK;
#pragma unroll
    for (int db = 0; db < 16; db++) {
        int col = db * 8 + 2 * q;
        *(__half2*)(Op + col) = __floats2half2_rn(oA[db][0] * inv0, oA[db][1] * inv0);
        *(__half2*)(Op + (size_t)8 * DMODEL + col) =
            __floats2half2_rn(oA[db][2] * inv1, oA[db][3] * inv1);
    }
}

// ---------------------------------------------------------------------------
extern "C" void kernel_launch(void* const* d_in, const int* in_sizes, int n_in,
                              void* d_out, int out_size)
{
    const float* x   = (const float*)d_in[0];
    const float* W_q = (const float*)d_in[1];
    const float* b_q = (const float*)d_in[2];
    const float* W_k = (const float*)d_in[3];
    const float* b_k = (const float*)d_in[4];
    const float* W_v = (const float*)d_in[5];
    const float* b_v = (const float*)d_in[6];
    const float* W_o = (const float*)d_in[7];
    const float* b_o = (const float*)d_in[8];

    float* out = (float*)d_out;
    float* Kc  = out + (size_t)MTOT * DMODEL;
    float* Vc  = Kc  + (size_t)MTOT * DKK;

    __half* ah = nullptr;
    cudaGetSymbolAddress((void**)&ah, g_ah);

    cudaFuncSetAttribute(kv_flash, cudaFuncAttributeMaxDynamicSharedMemorySize, FLASH_SMEM);
    cudaFuncSetAttribute(gemm_o,   cudaFuncAttributeMaxDynamicSharedMemorySize, GEMM_SMEM);

    // 1/sqrt(128) * log2(e): softmax computed with exp2
    const float qscale = 0.08838834764831845f * 1.4426950408889634f;

    // all fp32->fp16 conversions + kv-flag reset
    f2h_all<<<(int)(F2H_TOTAL / 4 / 256), 256>>>(x, W_q, W_k, W_v, W_o);

    // combined: K/V projection (CTAs 0-255, wave-1) + flash (CTAs 256-1279)
    kv_flash<<<KV_CTAS + SEQ / 64 * NHEADS * BATCH, 128, FLASH_SMEM>>>(
        b_q, b_k, b_v, Kc, Vc, qscale);

    // output projection -> out (fp32 + bias)
    gemm_o<<<dim3(DMODEL / 128, MTOT / 64), 128, GEMM_SMEM>>>(ah, b_o, out);
}

// round 15
// speedup vs baseline: 1.2177x; 1.2177x over previous
#include <cuda_runtime.h>
#include <cuda_fp16.h>
#include <cstdint>

#define BATCH  2
#define SEQ    2048
#define DMODEL 2048
#define NHEADS 16
#define DKK    128
#define MTOT   (BATCH * SEQ)

#define N_X  ((size_t)MTOT * DMODEL)     // 8388608
#define N_WQ ((size_t)DMODEL * DMODEL)   // 4194304
#define N_WK ((size_t)DMODEL * DKK)      // 262144

// Scratch (allocation-free rule: device globals)
__device__ __half g_xh [N_X];
__device__ __half g_wqh[N_WQ];
__device__ __half g_wkh[N_WK];
__device__ __half g_wvh[N_WK];
__device__ __half g_woh[N_WQ];
__device__ __half g_kh [(size_t)MTOT * DKK];
__device__ __half g_vh [(size_t)MTOT * DKK];
__device__ __half g_ah [N_X];            // attention out fp16

// ---------------------------------------------------------------------------
// helpers
// ---------------------------------------------------------------------------
__device__ __forceinline__ uint32_t smem_u32(const void* p) {
    uint32_t a;
    asm("{ .reg .u64 t; cvta.to.shared.u64 t, %1; cvt.u32.u64 %0, t; }" : "=r"(a) : "l"(p));
    return a;
}
#define CP16(dst, src) \
    asm volatile("cp.async.cg.shared.global [%0], [%1], 16;" :: "r"(dst), "l"(src) : "memory")
#define CPCOMMIT() asm volatile("cp.async.commit_group;" ::: "memory")
#define CPWAIT(n)  asm volatile("cp.async.wait_group %0;" :: "n"(n) : "memory")

__device__ __forceinline__ void ldsm4(uint32_t* r, uint32_t a) {
    asm volatile("ldmatrix.sync.aligned.m8n8.x4.shared.b16 {%0,%1,%2,%3}, [%4];"
                 : "=r"(r[0]), "=r"(r[1]), "=r"(r[2]), "=r"(r[3]) : "r"(a));
}
__device__ __forceinline__ void ldsm4t(uint32_t* r, uint32_t a) {
    asm volatile("ldmatrix.sync.aligned.m8n8.x4.trans.shared.b16 {%0,%1,%2,%3}, [%4];"
                 : "=r"(r[0]), "=r"(r[1]), "=r"(r[2]), "=r"(r[3]) : "r"(a));
}
__device__ __forceinline__ void mma16816(float* d, const uint32_t* a, const uint32_t* b) {
    asm volatile(
        "mma.sync.aligned.m16n8k16.row.col.f32.f16.f16.f32 "
        "{%0,%1,%2,%3},{%4,%5,%6,%7},{%8,%9},{%0,%1,%2,%3};"
        : "+f"(d[0]), "+f"(d[1]), "+f"(d[2]), "+f"(d[3])
        : "r"(a[0]), "r"(a[1]), "r"(a[2]), "r"(a[3]), "r"(b[0]), "r"(b[1]));
}
__device__ __forceinline__ void mma16816b(float* d, const uint32_t* a,
                                          uint32_t b0, uint32_t b1) {
    asm volatile(
        "mma.sync.aligned.m16n8k16.row.col.f32.f16.f16.f32 "
        "{%0,%1,%2,%3},{%4,%5,%6,%7},{%8,%9},{%0,%1,%2,%3};"
        : "+f"(d[0]), "+f"(d[1]), "+f"(d[2]), "+f"(d[3])
        : "r"(a[0]), "r"(a[1]), "r"(a[2]), "r"(a[3]), "r"(b0), "r"(b1));
}
__device__ __forceinline__ uint32_t packh2(float lo, float hi) {
    __half2 h = __floats2half2_rn(lo, hi);
    return *(uint32_t*)&h;
}

// ---------------------------------------------------------------------------
// fused fp32 -> fp16: all five tensors, 8 floats (32B) per thread
// ---------------------------------------------------------------------------
#define F2H_TOTAL (N_X + N_WQ + N_WK + N_WK + N_WQ)   // 17301504

__global__ __launch_bounds__(256) void f2h_all(
    const float* __restrict__ x,  const float* __restrict__ wq,
    const float* __restrict__ wk, const float* __restrict__ wv,
    const float* __restrict__ wo)
{
    size_t i = ((size_t)blockIdx.x * 256 + threadIdx.x) * 8;
    const float* s;
    __half* d;
    size_t off;
    if (i < N_X)                            { s = x;  d = g_xh;  off = i; }
    else if (i < N_X + N_WQ)                { s = wq; d = g_wqh; off = i - N_X; }
    else if (i < N_X + N_WQ + N_WK)         { s = wk; d = g_wkh; off = i - N_X - N_WQ; }
    else if (i < N_X + N_WQ + 2 * N_WK)     { s = wv; d = g_wvh; off = i - N_X - N_WQ - N_WK; }
    else                                    { s = wo; d = g_woh; off = i - N_X - N_WQ - 2 * N_WK; }
    float4 v0 = *(const float4*)(s + off);
    float4 v1 = *(const float4*)(s + off + 4);
    __half2* dp = (__half2*)(d + off);
    dp[0] = __floats2half2_rn(v0.x, v0.y);
    dp[1] = __floats2half2_rn(v0.z, v0.w);
    dp[2] = __floats2half2_rn(v1.x, v1.y);
    dp[3] = __floats2half2_rn(v1.z, v1.w);
}

// ---------------------------------------------------------------------------
// GEMM tile geometry: 4-stage cp.async ring, register-pipelined fragments.
// ---------------------------------------------------------------------------
#define GS_A 5120             // 64 rows * 80B
#define GS_B 8704             // 32 rows * 272B
#define GS_STAGE (GS_A + GS_B)    // 13824
#define GEMM_SMEM (4 * GS_STAGE)  // 55296

// BM=32 variant (for K/V projection: more CTAs -> full chip)
#define G32_A 2560            // 32 rows * 80B
#define G32_STAGE (G32_A + GS_B)  // 11264
#define G32_SMEM (4 * G32_STAGE)  // 45056

#define GEMM_MAINLOOP()                                                        \
    stage(0, 0); CPCOMMIT();                                                   \
    stage(1, 1); CPCOMMIT();                                                   \
    stage(2, 2); CPCOMMIT();                                                   \
    CPWAIT(2); __syncthreads();                                                \
    ldfr(0, 0);                                                                \
    for (int c = 0; c < NC; c += 2) {                                          \
        CPWAIT(1); __syncthreads();                                            \
        ldfr(1, (c + 1) & 3);                                                  \
        if (c + 3 < NC) stage(c + 3, (c + 3) & 3);                             \
        CPCOMMIT();                                                            \
        domma(0);                                                              \
        if (c + 2 < NC) {                                                      \
            CPWAIT(1); __syncthreads();                                        \
            ldfr(0, (c + 2) & 3);                                              \
        }                                                                      \
        if (c + 4 < NC) stage(c + 4, (c + 4) & 3);                             \
        CPCOMMIT();                                                            \
        domma(1);                                                              \
    }

// ---------------------------------------------------------------------------
// K/V projection, BM=32 (Q is fused into flash): grid (2, MTOT/32) = 256 CTAs.
// ---------------------------------------------------------------------------
__global__ __launch_bounds__(128, 2) void gemm_kv(
    const __half* __restrict__ A,
    const float* __restrict__ b_k, const float* __restrict__ b_v,
    float* __restrict__ Kc, float* __restrict__ Vc)
{
    extern __shared__ char smc[];
    const uint32_t sb = smem_u32(smc);

    const int tid  = threadIdx.x;
    const int lane = tid & 31;
    const int wid  = tid >> 5;
    const int wm   = wid & 1;
    const int wn   = wid >> 1;
    const int K    = DMODEL;
    const int NC   = K / 32;
    const int rowBase = blockIdx.y * 32;

    const bool isK = blockIdx.x == 0;
    const __half* Bsel = isK ? g_wkh : g_wvh;
    const float* biasS = isK ? b_k : b_v;
    __half* Chf        = isK ? g_kh : g_vh;
    float* Cf          = isK ? Kc : Vc;
    const int N        = DKK;

    auto stage = [&](int c, int s) {
        const int k0 = c * 32;
        const uint32_t sA = sb + s * G32_STAGE;
        const uint32_t sB = sA + G32_A;
        {
            int r = tid >> 2, kc = tid & 3;
            CP16(sA + r * 80 + kc * 16, A + (size_t)(rowBase + r) * K + k0 + kc * 8);
        }
#pragma unroll
        for (int i = 0; i < 4; i++) {
            int ch = tid + 128 * i;
            int r = ch >> 4, nc = ch & 15;
            CP16(sB + r * 272 + nc * 16, Bsel + (size_t)(k0 + r) * N + nc * 8);
        }
    };

    float acc[8][4];
#pragma unroll
    for (int b = 0; b < 8; b++)
#pragma unroll
        for (int r = 0; r < 4; r++) acc[b][r] = 0.f;

    const uint32_t aOff = (wm * 16 + (lane & 15)) * 80 + (lane >> 4) * 16;
    const uint32_t bRow = (lane & 15) * 272;
    const uint32_t bCol = (wn * 64 + 8 * (lane >> 4)) * 2;

    uint32_t fa[2][2][4];
    uint32_t fb[2][2][4][4];

    auto ldfr = [&](int set, int bufi) {
        const uint32_t sA = sb + bufi * G32_STAGE;
        const uint32_t sB = sA + G32_A;
#pragma unroll
        for (int ks = 0; ks < 2; ks++) {
            ldsm4(fa[set][ks], sA + aOff + ks * 32);
#pragma unroll
            for (int nbp = 0; nbp < 4; nbp++)
                ldsm4t(fb[set][ks][nbp], sB + bRow + ks * 16 * 272 + bCol + nbp * 32);
        }
    };
    auto domma = [&](int set) {
#pragma unroll
        for (int ks = 0; ks < 2; ks++)
#pragma unroll
            for (int nbp = 0; nbp < 4; nbp++) {
                mma16816(acc[2 * nbp],     fa[set][ks], fb[set][ks][nbp]);
                mma16816(acc[2 * nbp + 1], fa[set][ks], fb[set][ks][nbp] + 2);
            }
    };

    GEMM_MAINLOOP();

    const int g = lane >> 2, q = lane & 3;
    const int row = rowBase + wm * 16 + g;
#pragma unroll
    for (int nb = 0; nb < 8; nb++) {
        int col = wn * 64 + nb * 8 + 2 * q;
        float b0 = biasS[col], b1 = biasS[col + 1];
        float v0 = acc[nb][0] + b0, v1 = acc[nb][1] + b1;
        float v2 = acc[nb][2] + b0, v3 = acc[nb][3] + b1;
        *(__half2*)(Chf + (size_t)row * N + col)       = __floats2half2_rn(v0, v1);
        *(__half2*)(Chf + (size_t)(row + 8) * N + col) = __floats2half2_rn(v2, v3);
        *(float2*)(Cf + (size_t)row * N + col)       = make_float2(v0, v1);
        *(float2*)(Cf + (size_t)(row + 8) * N + col) = make_float2(v2, v3);
    }
}

// ---------------------------------------------------------------------------
// Output projection GEMM: out(fp32) = ah @ woh + b_o  (BM=64, BN=128)
// ---------------------------------------------------------------------------
__global__ __launch_bounds__(128, 2) void gemm_o(
    const __half* __restrict__ A, const float* __restrict__ bias,
    float* __restrict__ C)
{
    extern __shared__ char smc[];
    const uint32_t sb = smem_u32(smc);

    const int tid  = threadIdx.x;
    const int lane = tid & 31;
    const int wid  = tid >> 5;
    const int wm   = wid & 1;
    const int wn   = wid >> 1;
    const int N = DMODEL, K = DMODEL, NC = K / 32;
    const int rowBase = blockIdx.y * 64;
    const int colBase = blockIdx.x * 128;

    auto stage = [&](int c, int s) {
        const int k0 = c * 32;
        const uint32_t sA = sb + s * GS_STAGE;
        const uint32_t sB = sA + GS_A;
#pragma unroll
        for (int i = 0; i < 2; i++) {
            int ch = tid + 128 * i;
            int r = ch >> 2, kc = ch & 3;
            CP16(sA + r * 80 + kc * 16, A + (size_t)(rowBase + r) * K + k0 + kc * 8);
        }
#pragma unroll
        for (int i = 0; i < 4; i++) {
            int ch = tid + 128 * i;
            int r = ch >> 4, nc = ch & 15;
            CP16(sB + r * 272 + nc * 16, g_woh + (size_t)(k0 + r) * N + colBase + nc * 8);
        }
    };

    float acc[2][8][4];
#pragma unroll
    for (int a = 0; a < 2; a++)
#pragma unroll
        for (int b = 0; b < 8; b++)
#pragma unroll
            for (int r = 0; r < 4; r++) acc[a][b][r] = 0.f;

    const uint32_t aOff = (wm * 32 + (lane & 15)) * 80 + (lane >> 4) * 16;
    const uint32_t bRow = (lane & 15) * 272;
    const uint32_t bCol = (wn * 64 + 8 * (lane >> 4)) * 2;

    uint32_t fa[2][2][2][4];
    uint32_t fb[2][2][4][4];

    auto ldfr = [&](int set, int bufi) {
        const uint32_t sA = sb + bufi * GS_STAGE;
        const uint32_t sB = sA + GS_A;
#pragma unroll
        for (int ks = 0; ks < 2; ks++) {
            ldsm4(fa[set][ks][0], sA + aOff + ks * 32);
            ldsm4(fa[set][ks][1], sA + aOff + 16 * 80 + ks * 32);
#pragma unroll
            for (int nbp = 0; nbp < 4; nbp++)
                ldsm4t(fb[set][ks][nbp], sB + bRow + ks * 16 * 272 + bCol + nbp * 32);
        }
    };
    auto domma = [&](int set) {
#pragma unroll
        for (int ks = 0; ks < 2; ks++)
#pragma unroll
            for (int nbp = 0; nbp < 4; nbp++) {
                mma16816(acc[0][2 * nbp],     fa[set][ks][0], fb[set][ks][nbp]);
                mma16816(acc[0][2 * nbp + 1], fa[set][ks][0], fb[set][ks][nbp] + 2);
                mma16816(acc[1][2 * nbp],     fa[set][ks][1], fb[set][ks][nbp]);
                mma16816(acc[1][2 * nbp + 1], fa[set][ks][1], fb[set][ks][nbp] + 2);
            }
    };

    GEMM_MAINLOOP();

    const int g = lane >> 2, q = lane & 3;
#pragma unroll
    for (int mb = 0; mb < 2; mb++) {
        int row = rowBase + wm * 32 + mb * 16 + g;
#pragma unroll
        for (int nb = 0; nb < 8; nb++) {
            int col = colBase + wn * 64 + nb * 8 + 2 * q;
            float b0 = bias[col], b1 = bias[col + 1];
            *(float2*)(C + (size_t)row * N + col) =
                make_float2(acc[mb][nb][0] + b0, acc[mb][nb][1] + b1);
            *(float2*)(C + (size_t)(row + 8) * N + col) =
                make_float2(acc[mb][nb][2] + b0, acc[mb][nb][3] + b1);
        }
    }
}

// ---------------------------------------------------------------------------
// fp16 flash attention (MQA) with FUSED Q-PROJECTION — exact R13 config:
// CTA = 128 thr (4 warps), BQ=64, __launch_bounds__(128,3) -> 3 CTAs/SM.
// ---------------------------------------------------------------------------
#define FITEM 17408                    // 64 rows * 272B
#define FQ_BYTES 17408
#define FLASH_SMEM (FQ_BYTES + 3 * FITEM)   // 69632 -> 3 CTAs/SM
#define NT (SEQ / 64)
#define QP_A 5120                      // x-chunk bytes within a ring buffer

__global__ __launch_bounds__(128, 3) void flash_h(
    const __half* __restrict__ Xh, const float* __restrict__ b_q,
    const __half* __restrict__ Kh, const __half* __restrict__ Vh,
    __half* __restrict__ Ah, float qscale)
{
    extern __shared__ char smc[];
    const uint32_t sb = smem_u32(smc);
    const uint32_t sQ = sb;
    const uint32_t sR = sb + FQ_BYTES;

    const int tid  = threadIdx.x;
    const int lane = tid & 31;
    const int wid  = tid >> 5;
    const int h  = blockIdx.y;
    const int b  = blockIdx.z;
    const int q0 = blockIdx.x * 64;
    const size_t kvbase = (size_t)b * SEQ;

    // ======================= fused Q projection ==========================
    {
        const int wm = wid & 1, wn = wid >> 1;
        const __half* Ax = Xh + (size_t)(b * SEQ + q0) * DMODEL;

        auto stageQ = [&](int c, int s) {
            const int k0 = c * 32;
            const uint32_t sA = sR + s * FITEM;
            const uint32_t sB = sA + QP_A;
#pragma unroll
            for (int i = 0; i < 2; i++) {
                int ch = tid + 128 * i;
                int r = ch >> 2, kc = ch & 3;
                CP16(sA + r * 80 + kc * 16, Ax + (size_t)r * DMODEL + k0 + kc * 8);
            }
#pragma unroll
            for (int i = 0; i < 4; i++) {
                int ch = tid + 128 * i;
                int r = ch >> 4, nc = ch & 15;
                CP16(sB + r * 272 + nc * 16,
                     g_wqh + (size_t)(k0 + r) * DMODEL + h * DKK + nc * 8);
            }
        };

        float acc[2][8][4];
#pragma unroll
        for (int a = 0; a < 2; a++)
#pragma unroll
            for (int bb = 0; bb < 8; bb++)
#pragma unroll
                for (int r = 0; r < 4; r++) acc[a][bb][r] = 0.f;

        const uint32_t aOff = (wm * 32 + (lane & 15)) * 80 + (lane >> 4) * 16;
        const uint32_t bRow = (lane & 15) * 272;
        const uint32_t bCol = (wn * 64 + 8 * (lane >> 4)) * 2;

        stageQ(0, 0); CPCOMMIT();
        stageQ(1, 1); CPCOMMIT();

        for (int c = 0; c < DMODEL / 32; c++) {
            CPWAIT(1);
            __syncthreads();
            const uint32_t sA = sR + (c & 1) * FITEM;
            const uint32_t sB = sA + QP_A;
#pragma unroll
            for (int ks = 0; ks < 2; ks++) {
                uint32_t a0[4], a1[4];
                ldsm4(a0, sA + aOff + ks * 32);
                ldsm4(a1, sA + aOff + 16 * 80 + ks * 32);
#pragma unroll
                for (int nbp = 0; nbp < 4; nbp++) {
                    uint32_t bf[4];
                    ldsm4t(bf, sB + bRow + ks * 16 * 272 + bCol + nbp * 32);
                    mma16816(acc[0][2 * nbp],     a0, bf);
                    mma16816(acc[0][2 * nbp + 1], a0, bf + 2);
                    mma16816(acc[1][2 * nbp],     a1, bf);
                    mma16816(acc[1][2 * nbp + 1], a1, bf + 2);
                }
            }
            __syncthreads();
            if (c + 2 < DMODEL / 32) stageQ(c + 2, c & 1);
            CPCOMMIT();
        }
        CPWAIT(0);

        // epilogue: bias + scale -> sQ (fp16, canonical row-major 272B rows)
        const int g = lane >> 2, q = lane & 3;
#pragma unroll
        for (int mb = 0; mb < 2; mb++) {
            int row = wm * 32 + mb * 16 + g;
#pragma unroll
            for (int nb = 0; nb < 8; nb++) {
                int col = wn * 64 + nb * 8 + 2 * q;
                float bq0 = b_q[h * DKK + col], bq1 = b_q[h * DKK + col + 1];
                *(__half2*)(smc + row * 272 + col * 2) =
                    __floats2half2_rn((acc[mb][nb][0] + bq0) * qscale,
                                      (acc[mb][nb][1] + bq1) * qscale);
                *(__half2*)(smc + (row + 8) * 272 + col * 2) =
                    __floats2half2_rn((acc[mb][nb][2] + bq0) * qscale,
                                      (acc[mb][nb][3] + bq1) * qscale);
            }
        }
        __syncthreads();
    }

    // ======================= K/V attention loop ==========================
    auto stageItem = [&](int j) {
        if (j < 2 * NT) {
            const uint32_t base = sR + (j % 3) * FITEM;
            const __half* src = (j & 1) ? Vh : Kh;
            const size_t rowg = kvbase + (size_t)(j >> 1) * 64;
#pragma unroll
            for (int i = 0; i < 8; i++) {
                int ch = tid + 128 * i;
                int r = ch >> 4, nc = ch & 15;
                CP16(base + r * 272 + nc * 16, src + (rowg + r) * DKK + nc * 8);
            }
        }
    };

    stageItem(0); CPCOMMIT();
    stageItem(1); CPCOMMIT();
    stageItem(2); CPCOMMIT();

    // persistent Q fragments from sQ
    uint32_t qf[8][4];
    {
        const uint32_t qB = sQ + (wid * 16 + (lane & 15)) * 272 + (lane >> 4) * 16;
#pragma unroll
        for (int ks = 0; ks < 8; ks++) ldsm4(qf[ks], qB + ks * 32);
    }

    CPWAIT(2);       // K0 ready
    __syncthreads();

    float oA[16][4];
#pragma unroll
    for (int i = 0; i < 16; i++)
#pragma unroll
        for (int r = 0; r < 4; r++) oA[i][r] = 0.f;
    float m0 = -1e30f, m1 = -1e30f, l0 = 0.f, l1 = 0.f;

    const uint32_t kOff = (lane & 15) * 272 + (lane >> 4) * 16;
    const uint32_t vRow = (lane & 15) * 272;
    const uint32_t vCol = (lane >> 4) * 16;

    for (int t = 0; t < NT; t++) {
        const uint32_t kB = sR + ((2 * t) % 3) * FITEM;
        const uint32_t vB = sR + ((2 * t + 1) % 3) * FITEM;

        if (t > 0) { CPWAIT(2); __syncthreads(); }

        float sC[8][4];
#pragma unroll
        for (int i = 0; i < 8; i++)
#pragma unroll
            for (int r = 0; r < 4; r++) sC[i][r] = 0.f;
#pragma unroll
        for (int ks = 0; ks < 8; ks++) {
#pragma unroll
            for (int nbp = 0; nbp < 4; nbp++) {
                uint32_t bf[4];
                ldsm4(bf, kB + nbp * 16 * 272 + kOff + ks * 32);
                mma16816b(sC[2 * nbp],     qf[ks], bf[0], bf[2]);
                mma16816b(sC[2 * nbp + 1], qf[ks], bf[1], bf[3]);
            }
        }

        float mx0 = -1e30f, mx1 = -1e30f;
#pragma unroll
        for (int nb = 0; nb < 8; nb++) {
            mx0 = fmaxf(mx0, fmaxf(sC[nb][0], sC[nb][1]));
            mx1 = fmaxf(mx1, fmaxf(sC[nb][2], sC[nb][3]));
        }
        mx0 = fmaxf(mx0, __shfl_xor_sync(0xffffffffu, mx0, 1));
        mx0 = fmaxf(mx0, __shfl_xor_sync(0xffffffffu, mx0, 2));
        mx1 = fmaxf(mx1, __shfl_xor_sync(0xffffffffu, mx1, 1));
        mx1 = fmaxf(mx1, __shfl_xor_sync(0xffffffffu, mx1, 2));
        float mn0 = fmaxf(m0, mx0), mn1 = fmaxf(m1, mx1);
        float cr0 = exp2f(m0 - mn0), cr1 = exp2f(m1 - mn1);
        m0 = mn0; m1 = mn1;
        float rs0 = 0.f, rs1 = 0.f;
#pragma unroll
        for (int nb = 0; nb < 8; nb++) {
            sC[nb][0] = exp2f(sC[nb][0] - mn0);
            sC[nb][1] = exp2f(sC[nb][1] - mn0);
            sC[nb][2] = exp2f(sC[nb][2] - mn1);
            sC[nb][3] = exp2f(sC[nb][3] - mn1);
            rs0 += sC[nb][0] + sC[nb][1];
            rs1 += sC[nb][2] + sC[nb][3];
        }
        rs0 += __shfl_xor_sync(0xffffffffu, rs0, 1);
        rs0 += __shfl_xor_sync(0xffffffffu, rs0, 2);
        rs1 += __shfl_xor_sync(0xffffffffu, rs1, 1);
        rs1 += __shfl_xor_sync(0xffffffffu, rs1, 2);
        l0 = l0 * cr0 + rs0;
        l1 = l1 * cr1 + rs1;
#pragma unroll
        for (int db = 0; db < 16; db++) {
            oA[db][0] *= cr0; oA[db][1] *= cr0;
            oA[db][2] *= cr1; oA[db][3] *= cr1;
        }

        uint32_t pf[4][4];
#pragma unroll
        for (int s = 0; s < 4; s++) {
            pf[s][0] = packh2(sC[2 * s][0],     sC[2 * s][1]);
            pf[s][1] = packh2(sC[2 * s][2],     sC[2 * s][3]);
            pf[s][2] = packh2(sC[2 * s + 1][0], sC[2 * s + 1][1]);
            pf[s][3] = packh2(sC[2 * s + 1][2], sC[2 * s + 1][3]);
        }

        __syncthreads();
        stageItem(2 * t + 3);
        CPCOMMIT();
        CPWAIT(2);
        __syncthreads();

#pragma unroll
        for (int s = 0; s < 4; s++) {
#pragma unroll
            for (int dbp = 0; dbp < 8; dbp++) {
                uint32_t vf[4];
                ldsm4t(vf, vB + s * 16 * 272 + vRow + (dbp * 16) * 2 + vCol);
                mma16816(oA[2 * dbp],     pf[s], vf);
                mma16816(oA[2 * dbp + 1], pf[s], vf + 2);
            }
        }

        __syncthreads();
        stageItem(2 * t + 4);
        CPCOMMIT();
    }

    const float inv0 = 1.f / l0, inv1 = 1.f / l1;
    const int g = lane >> 2, q = lane & 3;
    const int row = q0 + wid * 16 + g;
    __half* Op = Ah + (size_t)(b * SEQ + row) * DMODEL + h * DKK;
#pragma unroll
    for (int db = 0; db < 16; db++) {
        int col = db * 8 + 2 * q;
        *(__half2*)(Op + col) = __floats2half2_rn(oA[db][0] * inv0, oA[db][1] * inv0);
        *(__half2*)(Op + (size_t)8 * DMODEL + col) =
            __floats2half2_rn(oA[db][2] * inv1, oA[db][3] * inv1);
    }
}

// ---------------------------------------------------------------------------
extern "C" void kernel_launch(void* const* d_in, const int* in_sizes, int n_in,
                              void* d_out, int out_size)
{
    const float* x   = (const float*)d_in[0];
    const float* W_q = (const float*)d_in[1];
    const float* b_q = (const float*)d_in[2];
    const float* W_k = (const float*)d_in[3];
    const float* b_k = (const float*)d_in[4];
    const float* W_v = (const float*)d_in[5];
    const float* b_v = (const float*)d_in[6];
    const float* W_o = (const float*)d_in[7];
    const float* b_o = (const float*)d_in[8];

    float* out = (float*)d_out;
    float* Kc  = out + (size_t)MTOT * DMODEL;
    float* Vc  = Kc  + (size_t)MTOT * DKK;

    __half *xh, *kh, *vh, *ah;
    cudaGetSymbolAddress((void**)&xh, g_xh);
    cudaGetSymbolAddress((void**)&kh, g_kh);
    cudaGetSymbolAddress((void**)&vh, g_vh);
    cudaGetSymbolAddress((void**)&ah, g_ah);

    cudaFuncSetAttribute(gemm_kv, cudaFuncAttributeMaxDynamicSharedMemorySize, G32_SMEM);
    cudaFuncSetAttribute(gemm_o,  cudaFuncAttributeMaxDynamicSharedMemorySize, GEMM_SMEM);
    cudaFuncSetAttribute(flash_h, cudaFuncAttributeMaxDynamicSharedMemorySize, FLASH_SMEM);

    // 1/sqrt(128) * log2(e): softmax computed with exp2
    const float qscale = 0.08838834764831845f * 1.4426950408889634f;

    // all fp32->fp16 conversions, 32B per thread
    f2h_all<<<(int)(F2H_TOTAL / 8 / 256), 256>>>(x, W_q, W_k, W_v, W_o);

    // K + V projections, BM=32 -> 256 CTAs (near-full chip)
    gemm_kv<<<dim3(2, MTOT / 32), 128, G32_SMEM>>>(xh, b_k, b_v, Kc, Vc);

    // flash attention with fused Q projection (3 CTAs/SM, R13 config)
    flash_h<<<dim3(SEQ / 64, NHEADS, BATCH), 128, FLASH_SMEM>>>(
        xh, b_q, kh, vh, ah, qscale);

    // output projection -> out (fp32 + bias)
    gemm_o<<<dim3(DMODEL / 128, MTOT / 64), 128, GEMM_SMEM>>>(ah, b_o, out);
}

// round 16
// speedup vs baseline: 1.2618x; 1.0362x over previous
#include <cuda_runtime.h>
#include <cuda_fp16.h>
#include <cstdint>

#define BATCH  2
#define SEQ    2048
#define DMODEL 2048
#define NHEADS 16
#define DKK    128
#define MTOT   (BATCH * SEQ)

#define N_X  ((size_t)MTOT * DMODEL)     // 8388608
#define N_WQ ((size_t)DMODEL * DMODEL)   // 4194304
#define N_WK ((size_t)DMODEL * DKK)      // 262144

// Scratch (allocation-free rule: device globals)
__device__ __half g_xh [N_X];
__device__ __half g_wqh[N_WQ];
__device__ __half g_wkh[N_WK];
__device__ __half g_wvh[N_WK];
__device__ __half g_woh[N_WQ];
__device__ __half g_kh [(size_t)MTOT * DKK];
__device__ __half g_vh [(size_t)MTOT * DKK];
__device__ __half g_ah [N_X];            // attention out fp16

// ---------------------------------------------------------------------------
// helpers
// ---------------------------------------------------------------------------
__device__ __forceinline__ uint32_t smem_u32(const void* p) {
    uint32_t a;
    asm("{ .reg .u64 t; cvta.to.shared.u64 t, %1; cvt.u32.u64 %0, t; }" : "=r"(a) : "l"(p));
    return a;
}
#define CP16(dst, src) \
    asm volatile("cp.async.cg.shared.global [%0], [%1], 16;" :: "r"(dst), "l"(src) : "memory")
#define CPCOMMIT() asm volatile("cp.async.commit_group;" ::: "memory")
#define CPWAIT(n)  asm volatile("cp.async.wait_group %0;" :: "n"(n) : "memory")

__device__ __forceinline__ void ldsm4(uint32_t* r, uint32_t a) {
    asm volatile("ldmatrix.sync.aligned.m8n8.x4.shared.b16 {%0,%1,%2,%3}, [%4];"
                 : "=r"(r[0]), "=r"(r[1]), "=r"(r[2]), "=r"(r[3]) : "r"(a));
}
__device__ __forceinline__ void ldsm4t(uint32_t* r, uint32_t a) {
    asm volatile("ldmatrix.sync.aligned.m8n8.x4.trans.shared.b16 {%0,%1,%2,%3}, [%4];"
                 : "=r"(r[0]), "=r"(r[1]), "=r"(r[2]), "=r"(r[3]) : "r"(a));
}
__device__ __forceinline__ void mma16816(float* d, const uint32_t* a, const uint32_t* b) {
    asm volatile(
        "mma.sync.aligned.m16n8k16.row.col.f32.f16.f16.f32 "
        "{%0,%1,%2,%3},{%4,%5,%6,%7},{%8,%9},{%0,%1,%2,%3};"
        : "+f"(d[0]), "+f"(d[1]), "+f"(d[2]), "+f"(d[3])
        : "r"(a[0]), "r"(a[1]), "r"(a[2]), "r"(a[3]), "r"(b[0]), "r"(b[1]));
}
__device__ __forceinline__ void mma16816b(float* d, const uint32_t* a,
                                          uint32_t b0, uint32_t b1) {
    asm volatile(
        "mma.sync.aligned.m16n8k16.row.col.f32.f16.f16.f32 "
        "{%0,%1,%2,%3},{%4,%5,%6,%7},{%8,%9},{%0,%1,%2,%3};"
        : "+f"(d[0]), "+f"(d[1]), "+f"(d[2]), "+f"(d[3])
        : "r"(a[0]), "r"(a[1]), "r"(a[2]), "r"(a[3]), "r"(b0), "r"(b1));
}
__device__ __forceinline__ uint32_t packh2(float lo, float hi) {
    __half2 h = __floats2half2_rn(lo, hi);
    return *(uint32_t*)&h;
}

// ---------------------------------------------------------------------------
// fused fp32 -> fp16: all five tensors, 8 floats (32B) per thread
// ---------------------------------------------------------------------------
#define F2H_TOTAL (N_X + N_WQ + N_WK + N_WK + N_WQ)   // 17301504

__global__ __launch_bounds__(256) void f2h_all(
    const float* __restrict__ x,  const float* __restrict__ wq,
    const float* __restrict__ wk, const float* __restrict__ wv,
    const float* __restrict__ wo)
{
    size_t i = ((size_t)blockIdx.x * 256 + threadIdx.x) * 8;
    const float* s;
    __half* d;
    size_t off;
    if (i < N_X)                            { s = x;  d = g_xh;  off = i; }
    else if (i < N_X + N_WQ)                { s = wq; d = g_wqh; off = i - N_X; }
    else if (i < N_X + N_WQ + N_WK)         { s = wk; d = g_wkh; off = i - N_X - N_WQ; }
    else if (i < N_X + N_WQ + 2 * N_WK)     { s = wv; d = g_wvh; off = i - N_X - N_WQ - N_WK; }
    else                                    { s = wo; d = g_woh; off = i - N_X - N_WQ - 2 * N_WK; }
    float4 v0 = *(const float4*)(s + off);
    float4 v1 = *(const float4*)(s + off + 4);
    __half2* dp = (__half2*)(d + off);
    dp[0] = __floats2half2_rn(v0.x, v0.y);
    dp[1] = __floats2half2_rn(v0.z, v0.w);
    dp[2] = __floats2half2_rn(v1.x, v1.y);
    dp[3] = __floats2half2_rn(v1.z, v1.w);
}

// ---------------------------------------------------------------------------
// GEMM tile geometry: 4-stage cp.async ring.
// ---------------------------------------------------------------------------
#define GS_A 5120             // 64 rows * 80B
#define GS_B 8704             // 32 rows * 272B
#define GS_STAGE (GS_A + GS_B)    // 13824
#define GEMM_SMEM (4 * GS_STAGE)  // 55296

// BM=32 variant (for K/V projection: more CTAs -> full chip)
#define G32_A 2560            // 32 rows * 80B
#define G32_STAGE (G32_A + GS_B)  // 11264
#define G32_SMEM (4 * G32_STAGE)  // 45056

#define GEMM_MAINLOOP()                                                        \
    stage(0, 0); CPCOMMIT();                                                   \
    stage(1, 1); CPCOMMIT();                                                   \
    stage(2, 2); CPCOMMIT();                                                   \
    CPWAIT(2); __syncthreads();                                                \
    ldfr(0, 0);                                                                \
    for (int c = 0; c < NC; c += 2) {                                          \
        CPWAIT(1); __syncthreads();                                            \
        ldfr(1, (c + 1) & 3);                                                  \
        if (c + 3 < NC) stage(c + 3, (c + 3) & 3);                             \
        CPCOMMIT();                                                            \
        domma(0);                                                              \
        if (c + 2 < NC) {                                                      \
            CPWAIT(1); __syncthreads();                                        \
            ldfr(0, (c + 2) & 3);                                              \
        }                                                                      \
        if (c + 4 < NC) stage(c + 4, (c + 4) & 3);                             \
        CPCOMMIT();                                                            \
        domma(1);                                                              \
    }

// ---------------------------------------------------------------------------
// K/V projection, BM=32 (Q is fused into flash): grid (2, MTOT/32) = 256 CTAs.
// (unchanged from R15)
// ---------------------------------------------------------------------------
__global__ __launch_bounds__(128, 2) void gemm_kv(
    const __half* __restrict__ A,
    const float* __restrict__ b_k, const float* __restrict__ b_v,
    float* __restrict__ Kc, float* __restrict__ Vc)
{
    extern __shared__ char smc[];
    const uint32_t sb = smem_u32(smc);

    const int tid  = threadIdx.x;
    const int lane = tid & 31;
    const int wid  = tid >> 5;
    const int wm   = wid & 1;
    const int wn   = wid >> 1;
    const int K    = DMODEL;
    const int NC   = K / 32;
    const int rowBase = blockIdx.y * 32;

    const bool isK = blockIdx.x == 0;
    const __half* Bsel = isK ? g_wkh : g_wvh;
    const float* biasS = isK ? b_k : b_v;
    __half* Chf        = isK ? g_kh : g_vh;
    float* Cf          = isK ? Kc : Vc;
    const int N        = DKK;

    auto stage = [&](int c, int s) {
        const int k0 = c * 32;
        const uint32_t sA = sb + s * G32_STAGE;
        const uint32_t sB = sA + G32_A;
        {
            int r = tid >> 2, kc = tid & 3;
            CP16(sA + r * 80 + kc * 16, A + (size_t)(rowBase + r) * K + k0 + kc * 8);
        }
#pragma unroll
        for (int i = 0; i < 4; i++) {
            int ch = tid + 128 * i;
            int r = ch >> 4, nc = ch & 15;
            CP16(sB + r * 272 + nc * 16, Bsel + (size_t)(k0 + r) * N + nc * 8);
        }
    };

    float acc[8][4];
#pragma unroll
    for (int b = 0; b < 8; b++)
#pragma unroll
        for (int r = 0; r < 4; r++) acc[b][r] = 0.f;

    const uint32_t aOff = (wm * 16 + (lane & 15)) * 80 + (lane >> 4) * 16;
    const uint32_t bRow = (lane & 15) * 272;
    const uint32_t bCol = (wn * 64 + 8 * (lane >> 4)) * 2;

    uint32_t fa[2][2][4];
    uint32_t fb[2][2][4][4];

    auto ldfr = [&](int set, int bufi) {
        const uint32_t sA = sb + bufi * G32_STAGE;
        const uint32_t sB = sA + G32_A;
#pragma unroll
        for (int ks = 0; ks < 2; ks++) {
            ldsm4(fa[set][ks], sA + aOff + ks * 32);
#pragma unroll
            for (int nbp = 0; nbp < 4; nbp++)
                ldsm4t(fb[set][ks][nbp], sB + bRow + ks * 16 * 272 + bCol + nbp * 32);
        }
    };
    auto domma = [&](int set) {
#pragma unroll
        for (int ks = 0; ks < 2; ks++)
#pragma unroll
            for (int nbp = 0; nbp < 4; nbp++) {
                mma16816(acc[2 * nbp],     fa[set][ks], fb[set][ks][nbp]);
                mma16816(acc[2 * nbp + 1], fa[set][ks], fb[set][ks][nbp] + 2);
            }
    };

    GEMM_MAINLOOP();

    const int g = lane >> 2, q = lane & 3;
    const int row = rowBase + wm * 16 + g;
#pragma unroll
    for (int nb = 0; nb < 8; nb++) {
        int col = wn * 64 + nb * 8 + 2 * q;
        float b0 = biasS[col], b1 = biasS[col + 1];
        float v0 = acc[nb][0] + b0, v1 = acc[nb][1] + b1;
        float v2 = acc[nb][2] + b0, v3 = acc[nb][3] + b1;
        *(__half2*)(Chf + (size_t)row * N + col)       = __floats2half2_rn(v0, v1);
        *(__half2*)(Chf + (size_t)(row + 8) * N + col) = __floats2half2_rn(v2, v3);
        *(float2*)(Cf + (size_t)row * N + col)       = make_float2(v0, v1);
        *(float2*)(Cf + (size_t)(row + 8) * N + col) = make_float2(v2, v3);
    }
}

// ---------------------------------------------------------------------------
// Output projection GEMM: out(fp32) = ah @ woh + b_o  (BM=64, BN=128)
// SINGLE fragment set (R9 pipeline proven neutral) -> regs ~140 ->
// __launch_bounds__(128,3) -> 3 CTAs/SM (12 warps).
// ---------------------------------------------------------------------------
__global__ __launch_bounds__(128, 3) void gemm_o(
    const __half* __restrict__ A, const float* __restrict__ bias,
    float* __restrict__ C)
{
    extern __shared__ char smc[];
    const uint32_t sb = smem_u32(smc);

    const int tid  = threadIdx.x;
    const int lane = tid & 31;
    const int wid  = tid >> 5;
    const int wm   = wid & 1;
    const int wn   = wid >> 1;
    const int N = DMODEL, K = DMODEL, NC = K / 32;
    const int rowBase = blockIdx.y * 64;
    const int colBase = blockIdx.x * 128;

    auto stage = [&](int c, int s) {
        const int k0 = c * 32;
        const uint32_t sA = sb + s * GS_STAGE;
        const uint32_t sB = sA + GS_A;
#pragma unroll
        for (int i = 0; i < 2; i++) {
            int ch = tid + 128 * i;
            int r = ch >> 2, kc = ch & 3;
            CP16(sA + r * 80 + kc * 16, A + (size_t)(rowBase + r) * K + k0 + kc * 8);
        }
#pragma unroll
        for (int i = 0; i < 4; i++) {
            int ch = tid + 128 * i;
            int r = ch >> 4, nc = ch & 15;
            CP16(sB + r * 272 + nc * 16, g_woh + (size_t)(k0 + r) * N + colBase + nc * 8);
        }
    };

    float acc[2][8][4];
#pragma unroll
    for (int a = 0; a < 2; a++)
#pragma unroll
        for (int b = 0; b < 8; b++)
#pragma unroll
            for (int r = 0; r < 4; r++) acc[a][b][r] = 0.f;

    const uint32_t aOff = (wm * 32 + (lane & 15)) * 80 + (lane >> 4) * 16;
    const uint32_t bRow = (lane & 15) * 272;
    const uint32_t bCol = (wn * 64 + 8 * (lane >> 4)) * 2;

    stage(0, 0); CPCOMMIT();
    stage(1, 1); CPCOMMIT();
    stage(2, 2); CPCOMMIT();

    for (int c = 0; c < NC; c++) {
        CPWAIT(2);
        __syncthreads();
        if (c + 3 < NC) stage(c + 3, (c + 3) & 3);
        CPCOMMIT();

        const uint32_t sA = sb + (c & 3) * GS_STAGE;
        const uint32_t sB = sA + GS_A;
#pragma unroll
        for (int ks = 0; ks < 2; ks++) {
            uint32_t a0[4], a1[4];
            ldsm4(a0, sA + aOff + ks * 32);
            ldsm4(a1, sA + aOff + 16 * 80 + ks * 32);
#pragma unroll
            for (int nbp = 0; nbp < 4; nbp++) {
                uint32_t bf[4];
                ldsm4t(bf, sB + bRow + ks * 16 * 272 + bCol + nbp * 32);
                mma16816(acc[0][2 * nbp],     a0, bf);
                mma16816(acc[0][2 * nbp + 1], a0, bf + 2);
                mma16816(acc[1][2 * nbp],     a1, bf);
                mma16816(acc[1][2 * nbp + 1], a1, bf + 2);
            }
        }
    }

    const int g = lane >> 2, q = lane & 3;
#pragma unroll
    for (int mb = 0; mb < 2; mb++) {
        int row = rowBase + wm * 32 + mb * 16 + g;
#pragma unroll
        for (int nb = 0; nb < 8; nb++) {
            int col = colBase + wn * 64 + nb * 8 + 2 * q;
            float b0 = bias[col], b1 = bias[col + 1];
            *(float2*)(C + (size_t)row * N + col) =
                make_float2(acc[mb][nb][0] + b0, acc[mb][nb][1] + b1);
            *(float2*)(C + (size_t)(row + 8) * N + col) =
                make_float2(acc[mb][nb][2] + b0, acc[mb][nb][3] + b1);
        }
    }
}

// ---------------------------------------------------------------------------
// fp16 flash attention (MQA) with FUSED Q-PROJECTION — R13 config, except
// the Q-proj ring is now 3 buffers with ONE barrier per chunk.
// CTA = 128 thr (4 warps), BQ=64, __launch_bounds__(128,3) -> 3 CTAs/SM.
// ---------------------------------------------------------------------------
#define FITEM 17408                    // 64 rows * 272B
#define FQ_BYTES 17408
#define FLASH_SMEM (FQ_BYTES + 3 * FITEM)   // 69632 -> 3 CTAs/SM
#define NT (SEQ / 64)
#define QP_A 5120                      // x-chunk bytes within a ring buffer

__global__ __launch_bounds__(128, 3) void flash_h(
    const __half* __restrict__ Xh, const float* __restrict__ b_q,
    const __half* __restrict__ Kh, const __half* __restrict__ Vh,
    __half* __restrict__ Ah, float qscale)
{
    extern __shared__ char smc[];
    const uint32_t sb = smem_u32(smc);
    const uint32_t sQ = sb;
    const uint32_t sR = sb + FQ_BYTES;

    const int tid  = threadIdx.x;
    const int lane = tid & 31;
    const int wid  = tid >> 5;
    const int h  = blockIdx.y;
    const int b  = blockIdx.z;
    const int q0 = blockIdx.x * 64;
    const size_t kvbase = (size_t)b * SEQ;

    // ======================= fused Q projection ==========================
    // 3-buffer ring, single barrier per chunk: at iteration c, buffer
    // (c+2)%3 == (c-1)%3 was consumed in iteration c-1; the sync at the top
    // of iteration c proves all threads are done with it before restaging.
    {
        const int wm = wid & 1, wn = wid >> 1;
        const __half* Ax = Xh + (size_t)(b * SEQ + q0) * DMODEL;

        auto stageQ = [&](int c, int s) {
            const int k0 = c * 32;
            const uint32_t sA = sR + s * FITEM;
            const uint32_t sB = sA + QP_A;
#pragma unroll
            for (int i = 0; i < 2; i++) {
                int ch = tid + 128 * i;
                int r = ch >> 2, kc = ch & 3;
                CP16(sA + r * 80 + kc * 16, Ax + (size_t)r * DMODEL + k0 + kc * 8);
            }
#pragma unroll
            for (int i = 0; i < 4; i++) {
                int ch = tid + 128 * i;
                int r = ch >> 4, nc = ch & 15;
                CP16(sB + r * 272 + nc * 16,
                     g_wqh + (size_t)(k0 + r) * DMODEL + h * DKK + nc * 8);
            }
        };

        float acc[2][8][4];
#pragma unroll
        for (int a = 0; a < 2; a++)
#pragma unroll
            for (int bb = 0; bb < 8; bb++)
#pragma unroll
                for (int r = 0; r < 4; r++) acc[a][bb][r] = 0.f;

        const uint32_t aOff = (wm * 32 + (lane & 15)) * 80 + (lane >> 4) * 16;
        const uint32_t bRow = (lane & 15) * 272;
        const uint32_t bCol = (wn * 64 + 8 * (lane >> 4)) * 2;

        stageQ(0, 0); CPCOMMIT();
        stageQ(1, 1); CPCOMMIT();

        for (int c = 0; c < DMODEL / 32; c++) {
            CPWAIT(1);
            __syncthreads();
            if (c + 2 < DMODEL / 32) stageQ(c + 2, (c + 2) % 3);
            CPCOMMIT();
            const uint32_t sA = sR + (c % 3) * FITEM;
            const uint32_t sB = sA + QP_A;
#pragma unroll
            for (int ks = 0; ks < 2; ks++) {
                uint32_t a0[4], a1[4];
                ldsm4(a0, sA + aOff + ks * 32);
                ldsm4(a1, sA + aOff + 16 * 80 + ks * 32);
#pragma unroll
                for (int nbp = 0; nbp < 4; nbp++) {
                    uint32_t bf[4];
                    ldsm4t(bf, sB + bRow + ks * 16 * 272 + bCol + nbp * 32);
                    mma16816(acc[0][2 * nbp],     a0, bf);
                    mma16816(acc[0][2 * nbp + 1], a0, bf + 2);
                    mma16816(acc[1][2 * nbp],     a1, bf);
                    mma16816(acc[1][2 * nbp + 1], a1, bf + 2);
                }
            }
        }
        CPWAIT(0);
        __syncthreads();   // ring drained before epilogue/attention reuse

        // epilogue: bias + scale -> sQ (fp16, canonical row-major 272B rows)
        const int g = lane >> 2, q = lane & 3;
#pragma unroll
        for (int mb = 0; mb < 2; mb++) {
            int row = wm * 32 + mb * 16 + g;
#pragma unroll
            for (int nb = 0; nb < 8; nb++) {
                int col = wn * 64 + nb * 8 + 2 * q;
                float bq0 = b_q[h * DKK + col], bq1 = b_q[h * DKK + col + 1];
                *(__half2*)(smc + row * 272 + col * 2) =
                    __floats2half2_rn((acc[mb][nb][0] + bq0) * qscale,
                                      (acc[mb][nb][1] + bq1) * qscale);
                *(__half2*)(smc + (row + 8) * 272 + col * 2) =
                    __floats2half2_rn((acc[mb][nb][2] + bq0) * qscale,
                                      (acc[mb][nb][3] + bq1) * qscale);
            }
        }
        __syncthreads();
    }

    // ======================= K/V attention loop ==========================
    auto stageItem = [&](int j) {
        if (j < 2 * NT) {
            const uint32_t base = sR + (j % 3) * FITEM;
            const __half* src = (j & 1) ? Vh : Kh;
            const size_t rowg = kvbase + (size_t)(j >> 1) * 64;
#pragma unroll
            for (int i = 0; i < 8; i++) {
                int ch = tid + 128 * i;
                int r = ch >> 4, nc = ch & 15;
                CP16(base + r * 272 + nc * 16, src + (rowg + r) * DKK + nc * 8);
            }
        }
    };

    stageItem(0); CPCOMMIT();
    stageItem(1); CPCOMMIT();
    stageItem(2); CPCOMMIT();

    // persistent Q fragments from sQ
    uint32_t qf[8][4];
    {
        const uint32_t qB = sQ + (wid * 16 + (lane & 15)) * 272 + (lane >> 4) * 16;
#pragma unroll
        for (int ks = 0; ks < 8; ks++) ldsm4(qf[ks], qB + ks * 32);
    }

    CPWAIT(2);       // K0 ready
    __syncthreads();

    float oA[16][4];
#pragma unroll
    for (int i = 0; i < 16; i++)
#pragma unroll
        for (int r = 0; r < 4; r++) oA[i][r] = 0.f;
    float m0 = -1e30f, m1 = -1e30f, l0 = 0.f, l1 = 0.f;

    const uint32_t kOff = (lane & 15) * 272 + (lane >> 4) * 16;
    const uint32_t vRow = (lane & 15) * 272;
    const uint32_t vCol = (lane >> 4) * 16;

    for (int t = 0; t < NT; t++) {
        const uint32_t kB = sR + ((2 * t) % 3) * FITEM;
        const uint32_t vB = sR + ((2 * t + 1) % 3) * FITEM;

        if (t > 0) { CPWAIT(2); __syncthreads(); }

        float sC[8][4];
#pragma unroll
        for (int i = 0; i < 8; i++)
#pragma unroll
            for (int r = 0; r < 4; r++) sC[i][r] = 0.f;
#pragma unroll
        for (int ks = 0; ks < 8; ks++) {
#pragma unroll
            for (int nbp = 0; nbp < 4; nbp++) {
                uint32_t bf[4];
                ldsm4(bf, kB + nbp * 16 * 272 + kOff + ks * 32);
                mma16816b(sC[2 * nbp],     qf[ks], bf[0], bf[2]);
                mma16816b(sC[2 * nbp + 1], qf[ks], bf[1], bf[3]);
            }
        }

        float mx0 = -1e30f, mx1 = -1e30f;
#pragma unroll
        for (int nb = 0; nb < 8; nb++) {
            mx0 = fmaxf(mx0, fmaxf(sC[nb][0], sC[nb][1]));
            mx1 = fmaxf(mx1, fmaxf(sC[nb][2], sC[nb][3]));
        }
        mx0 = fmaxf(mx0, __shfl_xor_sync(0xffffffffu, mx0, 1));
        mx0 = fmaxf(mx0, __shfl_xor_sync(0xffffffffu, mx0, 2));
        mx1 = fmaxf(mx1, __shfl_xor_sync(0xffffffffu, mx1, 1));
        mx1 = fmaxf(mx1, __shfl_xor_sync(0xffffffffu, mx1, 2));
        float mn0 = fmaxf(m0, mx0), mn1 = fmaxf(m1, mx1);
        float cr0 = exp2f(m0 - mn0), cr1 = exp2f(m1 - mn1);
        m0 = mn0; m1 = mn1;
        float rs0 = 0.f, rs1 = 0.f;
#pragma unroll
        for (int nb = 0; nb < 8; nb++) {
            sC[nb][0] = exp2f(sC[nb][0] - mn0);
            sC[nb][1] = exp2f(sC[nb][1] - mn0);
            sC[nb][2] = exp2f(sC[nb][2] - mn1);
            sC[nb][3] = exp2f(sC[nb][3] - mn1);
            rs0 += sC[nb][0] + sC[nb][1];
            rs1 += sC[nb][2] + sC[nb][3];
        }
        rs0 += __shfl_xor_sync(0xffffffffu, rs0, 1);
        rs0 += __shfl_xor_sync(0xffffffffu, rs0, 2);
        rs1 += __shfl_xor_sync(0xffffffffu, rs1, 1);
        rs1 += __shfl_xor_sync(0xffffffffu, rs1, 2);
        l0 = l0 * cr0 + rs0;
        l1 = l1 * cr1 + rs1;
#pragma unroll
        for (int db = 0; db < 16; db++) {
            oA[db][0] *= cr0; oA[db][1] *= cr0;
            oA[db][2] *= cr1; oA[db][3] *= cr1;
        }

        uint32_t pf[4][4];
#pragma unroll
        for (int s = 0; s < 4; s++) {
            pf[s][0] = packh2(sC[2 * s][0],     sC[2 * s][1]);
            pf[s][1] = packh2(sC[2 * s][2],     sC[2 * s][3]);
            pf[s][2] = packh2(sC[2 * s + 1][0], sC[2 * s + 1][1]);
            pf[s][3] = packh2(sC[2 * s + 1][2], sC[2 * s + 1][3]);
        }

        __syncthreads();
        stageItem(2 * t + 3);
        CPCOMMIT();
        CPWAIT(2);
        __syncthreads();

#pragma unroll
        for (int s = 0; s < 4; s++) {
#pragma unroll
            for (int dbp = 0; dbp < 8; dbp++) {
                uint32_t vf[4];
                ldsm4t(vf, vB + s * 16 * 272 + vRow + (dbp * 16) * 2 + vCol);
                mma16816(oA[2 * dbp],     pf[s], vf);
                mma16816(oA[2 * dbp + 1], pf[s], vf + 2);
            }
        }

        __syncthreads();
        stageItem(2 * t + 4);
        CPCOMMIT();
    }

    const float inv0 = 1.f / l0, inv1 = 1.f / l1;
    const int g = lane >> 2, q = lane & 3;
    const int row = q0 + wid * 16 + g;
    __half* Op = Ah + (size_t)(b * SEQ + row) * DMODEL + h * DKK;
#pragma unroll
    for (int db = 0; db < 16; db++) {
        int col = db * 8 + 2 * q;
        *(__half2*)(Op + col) = __floats2half2_rn(oA[db][0] * inv0, oA[db][1] * inv0);
        *(__half2*)(Op + (size_t)8 * DMODEL + col) =
            __floats2half2_rn(oA[db][2] * inv1, oA[db][3] * inv1);
    }
}

// ---------------------------------------------------------------------------
extern "C" void kernel_launch(void* const* d_in, const int* in_sizes, int n_in,
                              void* d_out, int out_size)
{
    const float* x   = (const float*)d_in[0];
    const float* W_q = (const float*)d_in[1];
    const float* b_q = (const float*)d_in[2];
    const float* W_k = (const float*)d_in[3];
    const float* b_k = (const float*)d_in[4];
    const float* W_v = (const float*)d_in[5];
    const float* b_v = (const float*)d_in[6];
    const float* W_o = (const float*)d_in[7];
    const float* b_o = (const float*)d_in[8];

    float* out = (float*)d_out;
    float* Kc  = out + (size_t)MTOT * DMODEL;
    float* Vc  = Kc  + (size_t)MTOT * DKK;

    __half *xh, *kh, *vh, *ah;
    cudaGetSymbolAddress((void**)&xh, g_xh);
    cudaGetSymbolAddress((void**)&kh, g_kh);
    cudaGetSymbolAddress((void**)&vh, g_vh);
    cudaGetSymbolAddress((void**)&ah, g_ah);

    cudaFuncSetAttribute(gemm_kv, cudaFuncAttributeMaxDynamicSharedMemorySize, G32_SMEM);
    cudaFuncSetAttribute(gemm_o,  cudaFuncAttributeMaxDynamicSharedMemorySize, GEMM_SMEM);
    cudaFuncSetAttribute(flash_h, cudaFuncAttributeMaxDynamicSharedMemorySize, FLASH_SMEM);

    // 1/sqrt(128) * log2(e): softmax computed with exp2
    const float qscale = 0.08838834764831845f * 1.4426950408889634f;

    // all fp32->fp16 conversions, 32B per thread
    f2h_all<<<(int)(F2H_TOTAL / 8 / 256), 256>>>(x, W_q, W_k, W_v, W_o);

    // K + V projections, BM=32 -> 256 CTAs (near-full chip)
    gemm_kv<<<dim3(2, MTOT / 32), 128, G32_SMEM>>>(xh, b_k, b_v, Kc, Vc);

    // flash attention with fused Q projection (3 CTAs/SM)
    flash_h<<<dim3(SEQ / 64, NHEADS, BATCH), 128, FLASH_SMEM>>>(
        xh, b_q, kh, vh, ah, qscale);

    // output projection -> out (fp32 + bias), now 3 CTAs/SM
    gemm_o<<<dim3(DMODEL / 128, MTOT / 64), 128, GEMM_SMEM>>>(ah, b_o, out);
}